// round 13
// baseline (speedup 1.0000x reference)
#include <cuda_runtime.h>
#include <cuda_bf16.h>
#include <math.h>

#define NU_  100000
#define NI_  50000
#define NT_  150000
#define NT4_ 600000          // 4 layers concatenated
#define D_   64
#define NNZ_ 2400000
#define NNZ4_ 9600000
#define BRI_ 50000
#define SCB4_ 586            // ceil(600000/1024)

// Hop buffers (bf16). Layer l occupies rows [l*NT_, (l+1)*NT_).
// h0 = g_Xh (initial embeddings), h1 = g_B1, h2 = g_B2, h3 = g_B3.
__device__ __nv_bfloat16 g_Xh[(size_t)NT4_ * D_];
__device__ __nv_bfloat16 g_B1[(size_t)NT4_ * D_];
__device__ __nv_bfloat16 g_B2[(size_t)NT4_ * D_];
__device__ __nv_bfloat16 g_B3[(size_t)NT4_ * D_];
// Unified CSR across 4 adjacencies
__device__ int  g_rowptr[NT4_ + 1];
__device__ int  g_cnt[NT4_];
__device__ int  g_pos[NT4_];
__device__ int2 g_edges[NNZ4_];  // (local col, float_bits(val))
__device__ int  g_bsum[SCB4_];
__device__ int  g_boff[SCB4_];
// Which rows' hop-3 outputs are actually consumed by the losses.
__device__ unsigned char g_mask[NT4_];
// Scalar accumulators + ordering flag
__device__ float g_scal[256];
__device__ int g_ordB;

struct Ptrs { const void* p[26]; };

__device__ __forceinline__ float sp_(float x) {  // softplus
    return (x > 15.f) ? x : log1pf(expf(x));
}

// acc(row) = 0.25*(h0 + h1 + h2 + h3); h0 from the fp32 input embedding,
// h1..h3 from the bf16 hop buffers at global row grow.
__device__ __forceinline__ float acc4_(const float* __restrict__ emb,
                                       size_t elocal, size_t grow, int d) {
    float h0 = emb[elocal * D_ + d];
    size_t o = grow * D_ + d;
    float h1 = __bfloat162float(g_B1[o]);
    float h2 = __bfloat162float(g_B2[o]);
    float h3 = __bfloat162float(g_B3[o]);
    return 0.25f * (h0 + h1 + h2 + h3);
}

// ---------------------------------------------------------------------------
// Zero scalar accumulators + detect input ordering by inspecting d_in[8]:
// int32 node ids < 150000 have bit patterns < 0x04000000; uniform floats don't.
__global__ void k_setup(const unsigned* __restrict__ p8) {
    int t = threadIdx.x;
    if (t < 256) g_scal[t] = 0.f;
    if (t == 0) {
        int fl = 0;
        for (int i = 0; i < 64; i++)
            if (p8[i] > 0x04000000u) fl++;
        g_ordB = (fl > 32) ? 1 : 0;
    }
}

// Batched: Xh(bf16) = concat(user_emb, item_emb) for all 4 layers;
// zero histogram + mask.
__global__ void __launch_bounds__(256) k_init(Ptrs P) {
    const int PL = NT_ * D_ / 8;  // 1.2M chunks per layer
    int i = blockIdx.x * 256 + threadIdx.x;
    if (i >= 4 * PL) return;
    if (i < NT4_) { g_cnt[i] = 0; g_mask[i] = 0; }
    int l = i / PL;
    int f = (i - l * PL) * 8;
    const float* eu = (const float*)P.p[2 * l];
    const float* ei = (const float*)P.p[2 * l + 1];
    const float* src = (f < NU_ * D_) ? (eu + f) : (ei + (f - NU_ * D_));
    float4 a = *(const float4*)(src);
    float4 b = *(const float4*)(src + 4);
    __nv_bfloat162 h[4];
    h[0] = __float22bfloat162_rn(make_float2(a.x, a.y));
    h[1] = __float22bfloat162_rn(make_float2(a.z, a.w));
    h[2] = __float22bfloat162_rn(make_float2(b.x, b.y));
    h[3] = __float22bfloat162_rn(make_float2(b.z, b.w));
    *(uint4*)(g_Xh + (size_t)l * NT_ * D_ + f) = *(uint4*)h;
}

// Mark the rows whose final-hop output is consumed by a loss.
__global__ void __launch_bounds__(256) k_mark(const int* __restrict__ user,
                                             const int* __restrict__ pos,
                                             const int* __restrict__ neg,
                                             const int* __restrict__ s_bri,
                                             const int* __restrict__ i_bri,
                                             const int* __restrict__ i_bri_pos) {
    int t = blockIdx.x * 256 + threadIdx.x;
    int r = -1;
    if      (t < 8192)           r = user[t];                       // L0 user
    else if (t < 16384)          r = NU_ + pos[t - 8192];           // L0 item
    else if (t < 24576)          r = NU_ + neg[t - 16384];          // L0 item
    else if (t < 28672)          r = s_bri[t - 24576];              // L0
    else if (t < 32768)          r = i_bri[t - 28672];              // L0
    else if (t < 36864)          r = NT_ + s_bri[t - 32768];        // L1
    else if (t < 40960)          r = NT_ + i_bri[t - 36864];        // L1
    else if (t < 45056)          r = 3 * NT_ + i_bri[t - 40960];    // L3 user
    else if (t < 49152)          r = 3 * NT_ + NU_ + i_bri_pos[t - 45056]; // L3 item
    else if (t < 99152)          r = 2 * NT_ + BRI_ + (t - 49152);  // L2 range
    if (r >= 0) g_mask[r] = 1;
}

// Batched histogram over all 4 adjacencies.
__global__ void __launch_bounds__(256) k_hist(Ptrs P) {
    int e = blockIdx.x * 256 + threadIdx.x;
    if (e >= NNZ4_) return;
    int l = e / NNZ_;
    int el = e - l * NNZ_;
    const int* rows = g_ordB ? (const int*)P.p[12 + 2 * l]
                             : (const int*)P.p[8 + 3 * l];
    atomicAdd(&g_cnt[l * NT_ + __ldcs(rows + el)], 1);
}

// Multi-block scan over 600K counts, phase A: per-block sums.
__global__ void __launch_bounds__(1024) k_scanA() {
    __shared__ int sm[1024];
    int t = threadIdx.x;
    int i = blockIdx.x * 1024 + t;
    sm[t] = (i < NT4_) ? g_cnt[i] : 0;
    __syncthreads();
    for (int s = 512; s; s >>= 1) {
        if (t < s) sm[t] += sm[t + s];
        __syncthreads();
    }
    if (t == 0) g_bsum[blockIdx.x] = sm[0];
}

// Phase B: single block scans the 586 block sums (exclusive).
__global__ void __launch_bounds__(1024) k_scanB() {
    __shared__ int sm[1024];
    int t = threadIdx.x;
    int v = (t < SCB4_) ? g_bsum[t] : 0;
    sm[t] = v;
    __syncthreads();
    for (int o = 1; o < 1024; o <<= 1) {
        int u = (t >= o) ? sm[t - o] : 0;
        __syncthreads();
        sm[t] += u;
        __syncthreads();
    }
    if (t < SCB4_) g_boff[t] = sm[t] - v;
}

// Phase C: per-block local scan + global offset -> rowptr, pos.
__global__ void __launch_bounds__(1024) k_scanC() {
    __shared__ int sm[1024];
    int t = threadIdx.x;
    int i = blockIdx.x * 1024 + t;
    int v = (i < NT4_) ? g_cnt[i] : 0;
    sm[t] = v;
    __syncthreads();
    for (int o = 1; o < 1024; o <<= 1) {
        int u = (t >= o) ? sm[t - o] : 0;
        __syncthreads();
        sm[t] += u;
        __syncthreads();
    }
    int excl = g_boff[blockIdx.x] + sm[t] - v;
    if (i < NT4_) {
        g_rowptr[i] = excl;
        g_pos[i] = excl;
    }
    if (i == NT4_ - 1) g_rowptr[NT4_] = excl + v;
}

// Batched scatter (fp-sum order nondeterminism ~1e-7, tol 1e-3).
__global__ void __launch_bounds__(256) k_scatter(Ptrs P) {
    int e = blockIdx.x * 256 + threadIdx.x;
    if (e >= NNZ4_) return;
    int l = e / NNZ_;
    int el = e - l * NNZ_;
    const int *rows, *cols;
    const float* vals;
    if (g_ordB) {
        rows = (const int*)P.p[12 + 2 * l];
        cols = (const int*)P.p[13 + 2 * l];
        vals = (const float*)P.p[8 + l];
    } else {
        rows = (const int*)P.p[8 + 3 * l];
        cols = (const int*)P.p[9 + 3 * l];
        vals = (const float*)P.p[10 + 3 * l];
    }
    int r = __ldcs(rows + el);
    int c = __ldcs(cols + el);
    float v = __ldcs(vals + el);
    int p = atomicAdd(&g_pos[l * NT_ + r], 1);
    g_edges[p] = make_int2(c, __float_as_int(v));
}

// Batched CSR SpMM + residual; writes the hop's own bf16 buffer.
// 8 lanes per row, 4 rows per warp. The warp's (contiguous) CSR edge span is
// staged through shared memory in chunks of 32: one coalesced LDG.64 per lane
// per 32 edges instead of one broadcast LDG.64 per lane per edge. Consumers
// read edges via conflict-free LDS broadcast. This cuts global-load issue
// (the suspected bottleneck) nearly 2x.
__global__ void __launch_bounds__(256) k_spmm_csr(int hop) {
    __shared__ int2 sme[8][32];
    int tid = blockIdx.x * 256 + threadIdx.x;
    int row = tid >> 3;                 // global row in [0, NT4_); grid exact
    int k = tid & 7;
    int lane = threadIdx.x & 31;
    int wid = threadIdx.x >> 5;
    int warpRow0 = (blockIdx.x * 256 + (wid << 5)) >> 3;  // first of 4 rows

    bool active = true;
    if (hop == 2) active = (g_mask[row] != 0);
    // whole-warp skip when no row of this warp is needed
    if (hop == 2 && __ballot_sync(0xffffffffu, active) == 0u) return;

    const __nv_bfloat16* xg = (hop == 0) ? g_Xh : ((hop == 1) ? g_B1 : g_B2);
    __nv_bfloat16* y = (hop == 0) ? g_B1 : ((hop == 1) ? g_B2 : g_B3);
    int l = row / NT_;
    const __nv_bfloat16* xb = xg + (size_t)l * NT_ * D_;

    int warpBase = g_rowptr[warpRow0];
    int warpEnd  = g_rowptr[min(warpRow0 + 4, NT4_)];
    int myS = g_rowptr[row];
    int myE = active ? g_rowptr[row + 1] : myS;

    float s[8] = {0.f, 0.f, 0.f, 0.f, 0.f, 0.f, 0.f, 0.f};
    for (int base = warpBase; base < warpEnd; base += 32) {
        int e = base + lane;
        if (e < warpEnd) sme[wid][lane] = __ldcs(&g_edges[e]);
        __syncwarp();
        int lo = max(myS, base);
        int hi = min(myE, base + 32);
#pragma unroll 4
        for (int j = lo; j < hi; j++) {
            int2 ed = sme[wid][j - base];   // broadcast within 8-lane group
            float vj = __int_as_float(ed.y);
            uint4 raw = *(const uint4*)(xb + ed.x * D_ + k * 8);
            const __nv_bfloat162* p = (const __nv_bfloat162*)&raw;
#pragma unroll
            for (int q = 0; q < 4; q++) {
                float2 f = __bfloat1622float2(p[q]);
                s[q * 2]     += vj * f.x;
                s[q * 2 + 1] += vj * f.y;
            }
        }
        __syncwarp();
    }
    if (!active) return;
    size_t ro = (size_t)row * D_ + k * 8;
    // residual: + h[row]
    {
        uint4 raw = *(const uint4*)(xg + ro);
        const __nv_bfloat162* p = (const __nv_bfloat162*)&raw;
#pragma unroll
        for (int q = 0; q < 4; q++) {
            float2 f = __bfloat1622float2(p[q]);
            s[q * 2]     += f.x;
            s[q * 2 + 1] += f.y;
        }
    }
    // store y (bf16)
    __nv_bfloat162 h[4];
#pragma unroll
    for (int q = 0; q < 4; q++)
        h[q] = __float22bfloat162_rn(make_float2(s[q * 2], s[q * 2 + 1]));
    *(uint4*)(y + ro) = *(uint4*)h;
}

// ---------------------------------------------------------------------------
// Loss kernels: reconstruct 0.25*(h0+h1+h2+h3) on the fly.

__global__ void __launch_bounds__(256) k_rating(const int* __restrict__ user,
                                                const int* __restrict__ pos,
                                                const int* __restrict__ neg,
                                                const float* __restrict__ ue,
                                                const float* __restrict__ ie) {
    int gt = blockIdx.x * 256 + threadIdx.x;
    int w = gt >> 5, lane = gt & 31;
    if (w >= 8192) return;
    int ur = user[w];
    int pr = pos[w];
    int nr = neg[w];
    float pp = 0.f, np = 0.f, l2 = 0.f;
#pragma unroll
    for (int q = 0; q < 2; q++) {
        int d = lane * 2 + q;
        float u = acc4_(ue, ur, ur, d);                  // layer 0, user
        float a = acc4_(ie, pr, (size_t)NU_ + pr, d);    // layer 0, item
        float b = acc4_(ie, nr, (size_t)NU_ + nr, d);
        pp += u * a;
        np += u * b;
        l2 += u * u + a * a + b * b;
    }
    for (int o = 16; o; o >>= 1) {
        pp += __shfl_down_sync(0xffffffffu, pp, o);
        np += __shfl_down_sync(0xffffffffu, np, o);
        l2 += __shfl_down_sync(0xffffffffu, l2, o);
    }
    if (lane == 0) atomicAdd(&g_scal[0], sp_(np - pp) + 0.01f * l2);
}

// Sum of -softplus(sign*acc) over 4096 gathered user rows of layer at rowoff.
__global__ void __launch_bounds__(256) k_brilog(const int* __restrict__ idx,
                                                const float* __restrict__ emb,
                                                int rowoff, float sign, int slot) {
    int t = blockIdx.x * 256 + threadIdx.x;  // exactly 4096*64 threads
    int i = t >> 6, d = t & 63;
    int r = idx[i];
    float x = acc4_(emb, r, (size_t)rowoff + r, d);
    float val = -sp_(sign * x);
    __shared__ float sm[256];
    sm[threadIdx.x] = val;
    __syncthreads();
    for (int s = 128; s; s >>= 1) {
        if (threadIdx.x < s) sm[threadIdx.x] += sm[threadIdx.x + s];
        __syncthreads();
    }
    if (threadIdx.x == 0) atomicAdd(&g_scal[slot], sm[0]);
}

// Column sums of acc over layer-2 user rows [BRI_, BRI_+50000) -> g_scal[8+d].
__global__ void __launch_bounds__(256) k_gsoc(const float* __restrict__ sgu) {
    int gt = blockIdx.x * 256 + threadIdx.x;  // 128 blocks -> 512 row groups
    int d = gt & 63;
    int rg = gt >> 6;
    const size_t base = (size_t)2 * NT_;  // layer 2 global row offset
    float s = 0.f;
    for (int r = BRI_ + rg; r < BRI_ + 50000; r += 512)
        s += acc4_(sgu, r, base + r, d);
    __shared__ float sm[256];
    sm[threadIdx.x] = s;
    __syncthreads();
    if (threadIdx.x < 64)
        atomicAdd(&g_scal[8 + threadIdx.x],
                  sm[threadIdx.x] + sm[threadIdx.x + 64] +
                  sm[threadIdx.x + 128] + sm[threadIdx.x + 192]);
}

// Column sums of sigmoid(acc) over 4096 gathered rows -> g_scal[slot+d].
__global__ void __launch_bounds__(256) k_gmean(const int* __restrict__ idx,
                                               const float* __restrict__ emb,
                                               int growoff, int slot) {
    int t = blockIdx.x * 256 + threadIdx.x;  // exactly 4096*64 threads
    int i = t >> 6, d = t & 63;
    int r = idx[i];
    float x = acc4_(emb, r, (size_t)growoff + r, d);
    float sg = 1.f / (1.f + expf(-x));
    __shared__ float sm[256];
    sm[threadIdx.x] = sg;
    __syncthreads();
    if (threadIdx.x < 64)
        atomicAdd(&g_scal[slot + threadIdx.x],
                  sm[threadIdx.x] + sm[threadIdx.x + 64] +
                  sm[threadIdx.x + 128] + sm[threadIdx.x + 192]);
}

__global__ void k_final(float* __restrict__ out) {
    double sgr = 0.0, sgf = 0.0, sir = 0.0, sif = 0.0;
    for (int d = 0; d < 64; d++) {
        double gs = (double)g_scal[8 + d] / 50000.0;
        double sg = 1.0 / (1.0 + exp(-gs));
        sgr += log(sg);
        sgf += log(1.0 - sg);
    }
    for (int d = 0; d < 128; d++) {
        double g = (double)g_scal[72 + d] / 4096.0;
        sir += log(g);
        sif += log1p(-g);
    }
    double A1 = g_scal[0], A2 = g_scal[1], A3 = g_scal[2];
    double A5 = g_scal[3], A6 = g_scal[4];
    double social = -(A2 / (4096.0 * 128.0) + sgr / 128.0)
                    - (A3 / (4096.0 * 128.0) + sgf / 128.0);
    double infor  = -(A5 / (4096.0 * 192.0) + sir / 192.0)
                    - (A6 / (4096.0 * 192.0) + sif / 192.0);
    double rating = A1;
    double obj = rating + 100.0 * social + 1000.0 * infor;
    out[0] = (float)obj;
    out[1] = (float)rating;
    out[2] = (float)social;
    out[3] = (float)infor;
}

extern "C" void kernel_launch(void* const* d_in, const int* in_sizes, int n_in,
                              void* d_out, int out_size) {
    Ptrs P;
    for (int i = 0; i < 26; i++) P.p[i] = d_in[i];
    const float* ue  = (const float*)d_in[0];
    const float* ie  = (const float*)d_in[1];
    const float* fue = (const float*)d_in[2];
    const float* sgu = (const float*)d_in[4];
    const float* igu = (const float*)d_in[6];
    const float* igi = (const float*)d_in[7];
    const int* user      = (const int*)d_in[20];
    const int* pos       = (const int*)d_in[21];
    const int* neg       = (const int*)d_in[22];
    const int* s_bri     = (const int*)d_in[23];
    const int* i_bri     = (const int*)d_in[24];
    const int* i_bri_pos = (const int*)d_in[25];

    k_setup<<<1, 256>>>((const unsigned*)d_in[8]);

    const int CHG4 = (NT4_ * D_ / 8 + 255) / 256;  // 18750
    const int EDG4 = (NNZ4_ + 255) / 256;          // 37500
    const int SPG4 = (NT4_ * 8) / 256;             // 18750 exact

    k_init<<<CHG4, 256>>>(P);
    k_mark<<<(99152 + 255) / 256, 256>>>(user, pos, neg, s_bri, i_bri, i_bri_pos);
    k_hist<<<EDG4, 256>>>(P);
    k_scanA<<<SCB4_, 1024>>>();
    k_scanB<<<1, 1024>>>();
    k_scanC<<<SCB4_, 1024>>>();
    k_scatter<<<EDG4, 256>>>(P);
    for (int hop = 0; hop < 3; hop++)
        k_spmm_csr<<<SPG4, 256>>>(hop);

    k_rating<<<1024, 256>>>(user, pos, neg, ue, ie);
    k_brilog<<<1024, 256>>>(s_bri, ue, 0, -1.f, 1);               // layer 0
    k_brilog<<<1024, 256>>>(i_bri, ue, 0, -1.f, 3);               // layer 0
    k_brilog<<<1024, 256>>>(s_bri, fue, NT_, 1.f, 2);             // layer 1
    k_brilog<<<1024, 256>>>(i_bri, fue, NT_, 1.f, 4);             // layer 1
    k_gsoc<<<128, 256>>>(sgu);                                    // layer 2
    k_gmean<<<1024, 256>>>(i_bri, igu, 3 * NT_, 72);              // layer 3 users
    k_gmean<<<1024, 256>>>(i_bri_pos, igi, 3 * NT_ + NU_, 136);   // layer 3 items
    k_final<<<1, 1>>>((float*)d_out);
}

// round 15
// speedup vs baseline: 1.3581x; 1.3581x over previous
#include <cuda_runtime.h>
#include <cuda_bf16.h>
#include <cuda_fp8.h>
#include <math.h>

#define NU_  100000
#define NI_  50000
#define NT_  150000
#define NT4_ 600000          // 4 layers concatenated
#define D_   64
#define NNZ_ 2400000
#define NNZ4_ 9600000
#define BRI_ 50000
#define SCB4_ 586            // ceil(600000/1024)

#define SCALE_   64.0f
#define SCALE_I  (1.0f / 64.0f)

// Hop buffers in e4m3 fp8, uniformly scaled by 64 (propagation is linear, so
// the scale passes through hops exactly; losses divide it out).
// h0 is re-read from the fp32 inputs at loss time; h1..h3 live here.
__device__ unsigned char g_X8[(size_t)NT4_ * D_];
__device__ unsigned char g_B1[(size_t)NT4_ * D_];
__device__ unsigned char g_B2[(size_t)NT4_ * D_];
__device__ unsigned char g_B3[(size_t)NT4_ * D_];
// Unified CSR across 4 adjacencies
__device__ int  g_rowptr[NT4_ + 1];
__device__ int  g_cnt[NT4_];
__device__ int  g_pos[NT4_];
__device__ int2 g_edges[NNZ4_];  // (local col, float_bits(val))
__device__ int  g_bsum[SCB4_];
__device__ int  g_boff[SCB4_];
// Which rows' hop-3 outputs are actually consumed by the losses.
__device__ unsigned char g_mask[NT4_];
// Scalar accumulators + ordering flag
__device__ float g_scal[256];
__device__ int g_ordB;

struct Ptrs { const void* p[26]; };

__device__ __forceinline__ float sp_(float x) {  // softplus
    return (x > 15.f) ? x : log1pf(expf(x));
}

__device__ __forceinline__ float fp8_to_f_(unsigned char v) {
    __half_raw h = __nv_cvt_fp8_to_halfraw((__nv_fp8_storage_t)v, __NV_E4M3);
    return __half2float(*(__half*)&h);
}

// Accumulate 4 fp8 dims (one 32-bit word) into s[0..3] with weight vj.
__device__ __forceinline__ void fp8x4_acc_(unsigned raw, float vj, float* s) {
    __half2_raw h0 = __nv_cvt_fp8x2_to_halfraw2(
        (__nv_fp8x2_storage_t)(raw & 0xFFFFu), __NV_E4M3);
    __half2_raw h1 = __nv_cvt_fp8x2_to_halfraw2(
        (__nv_fp8x2_storage_t)(raw >> 16), __NV_E4M3);
    float2 f0 = __half22float2(*(__half2*)&h0);
    float2 f1 = __half22float2(*(__half2*)&h1);
    s[0] += vj * f0.x;
    s[1] += vj * f0.y;
    s[2] += vj * f1.x;
    s[3] += vj * f1.y;
}

// Pack 4 floats into 4 fp8 bytes (one 32-bit word).
__device__ __forceinline__ unsigned f4_to_fp8x4_(float a, float b, float c, float d) {
    unsigned lo = __nv_cvt_float2_to_fp8x2(make_float2(a, b), __NV_SATFINITE, __NV_E4M3);
    unsigned hi = __nv_cvt_float2_to_fp8x2(make_float2(c, d), __NV_SATFINITE, __NV_E4M3);
    return (hi << 16) | (lo & 0xFFFFu);
}

// acc(row) = 0.25*(h0 + (h1+h2+h3)/64); h0 from the fp32 input embedding.
__device__ __forceinline__ float acc4_(const float* __restrict__ emb,
                                       size_t elocal, size_t grow, int d) {
    float h0 = emb[elocal * D_ + d];
    size_t o = grow * D_ + d;
    float h123 = fp8_to_f_(g_B1[o]) + fp8_to_f_(g_B2[o]) + fp8_to_f_(g_B3[o]);
    return 0.25f * (h0 + h123 * SCALE_I);
}

// ---------------------------------------------------------------------------
// Zero scalar accumulators + detect input ordering by inspecting d_in[8]:
// int32 node ids < 150000 have bit patterns < 0x04000000; uniform floats don't.
__global__ void k_setup(const unsigned* __restrict__ p8) {
    int t = threadIdx.x;
    if (t < 256) g_scal[t] = 0.f;
    if (t == 0) {
        int fl = 0;
        for (int i = 0; i < 64; i++)
            if (p8[i] > 0x04000000u) fl++;
        g_ordB = (fl > 32) ? 1 : 0;
    }
}

// Batched: X8(fp8, x64) = concat(user_emb, item_emb); zero histogram + mask.
__global__ void __launch_bounds__(256) k_init(Ptrs P) {
    const int PL = NT_ * D_ / 8;  // 1.2M chunks per layer
    int i = blockIdx.x * 256 + threadIdx.x;
    if (i >= 4 * PL) return;
    if (i < NT4_) { g_cnt[i] = 0; g_mask[i] = 0; }
    int l = i / PL;
    int f = (i - l * PL) * 8;
    const float* eu = (const float*)P.p[2 * l];
    const float* ei = (const float*)P.p[2 * l + 1];
    const float* src = (f < NU_ * D_) ? (eu + f) : (ei + (f - NU_ * D_));
    float4 a = *(const float4*)(src);
    float4 b = *(const float4*)(src + 4);
    uint2 o;
    o.x = f4_to_fp8x4_(a.x * SCALE_, a.y * SCALE_, a.z * SCALE_, a.w * SCALE_);
    o.y = f4_to_fp8x4_(b.x * SCALE_, b.y * SCALE_, b.z * SCALE_, b.w * SCALE_);
    *(uint2*)(g_X8 + (size_t)l * NT_ * D_ + f) = o;
}

// Mark the rows whose final-hop output is consumed by a loss.
__global__ void __launch_bounds__(256) k_mark(const int* __restrict__ user,
                                             const int* __restrict__ pos,
                                             const int* __restrict__ neg,
                                             const int* __restrict__ s_bri,
                                             const int* __restrict__ i_bri,
                                             const int* __restrict__ i_bri_pos) {
    int t = blockIdx.x * 256 + threadIdx.x;
    int r = -1;
    if      (t < 8192)           r = user[t];                       // L0 user
    else if (t < 16384)          r = NU_ + pos[t - 8192];           // L0 item
    else if (t < 24576)          r = NU_ + neg[t - 16384];          // L0 item
    else if (t < 28672)          r = s_bri[t - 24576];              // L0
    else if (t < 32768)          r = i_bri[t - 28672];              // L0
    else if (t < 36864)          r = NT_ + s_bri[t - 32768];        // L1
    else if (t < 40960)          r = NT_ + i_bri[t - 36864];        // L1
    else if (t < 45056)          r = 3 * NT_ + i_bri[t - 40960];    // L3 user
    else if (t < 49152)          r = 3 * NT_ + NU_ + i_bri_pos[t - 45056]; // L3 item
    else if (t < 99152)          r = 2 * NT_ + BRI_ + (t - 49152);  // L2 range
    if (r >= 0) g_mask[r] = 1;
}

// Batched histogram over all 4 adjacencies.
__global__ void __launch_bounds__(256) k_hist(Ptrs P) {
    int e = blockIdx.x * 256 + threadIdx.x;
    if (e >= NNZ4_) return;
    int l = e / NNZ_;
    int el = e - l * NNZ_;
    const int* rows = g_ordB ? (const int*)P.p[12 + 2 * l]
                             : (const int*)P.p[8 + 3 * l];
    atomicAdd(&g_cnt[l * NT_ + __ldcs(rows + el)], 1);
}

// Multi-block scan over 600K counts, phase A: per-block sums.
__global__ void __launch_bounds__(1024) k_scanA() {
    __shared__ int sm[1024];
    int t = threadIdx.x;
    int i = blockIdx.x * 1024 + t;
    sm[t] = (i < NT4_) ? g_cnt[i] : 0;
    __syncthreads();
    for (int s = 512; s; s >>= 1) {
        if (t < s) sm[t] += sm[t + s];
        __syncthreads();
    }
    if (t == 0) g_bsum[blockIdx.x] = sm[0];
}

// Phase B: single block scans the 586 block sums (exclusive).
__global__ void __launch_bounds__(1024) k_scanB() {
    __shared__ int sm[1024];
    int t = threadIdx.x;
    int v = (t < SCB4_) ? g_bsum[t] : 0;
    sm[t] = v;
    __syncthreads();
    for (int o = 1; o < 1024; o <<= 1) {
        int u = (t >= o) ? sm[t - o] : 0;
        __syncthreads();
        sm[t] += u;
        __syncthreads();
    }
    if (t < SCB4_) g_boff[t] = sm[t] - v;
}

// Phase C: per-block local scan + global offset -> rowptr, pos.
__global__ void __launch_bounds__(1024) k_scanC() {
    __shared__ int sm[1024];
    int t = threadIdx.x;
    int i = blockIdx.x * 1024 + t;
    int v = (i < NT4_) ? g_cnt[i] : 0;
    sm[t] = v;
    __syncthreads();
    for (int o = 1; o < 1024; o <<= 1) {
        int u = (t >= o) ? sm[t - o] : 0;
        __syncthreads();
        sm[t] += u;
        __syncthreads();
    }
    int excl = g_boff[blockIdx.x] + sm[t] - v;
    if (i < NT4_) {
        g_rowptr[i] = excl;
        g_pos[i] = excl;
    }
    if (i == NT4_ - 1) g_rowptr[NT4_] = excl + v;
}

// Batched scatter (fp-sum order nondeterminism ~1e-7, tol 1e-3).
__global__ void __launch_bounds__(256) k_scatter(Ptrs P) {
    int e = blockIdx.x * 256 + threadIdx.x;
    if (e >= NNZ4_) return;
    int l = e / NNZ_;
    int el = e - l * NNZ_;
    const int *rows, *cols;
    const float* vals;
    if (g_ordB) {
        rows = (const int*)P.p[12 + 2 * l];
        cols = (const int*)P.p[13 + 2 * l];
        vals = (const float*)P.p[8 + l];
    } else {
        rows = (const int*)P.p[8 + 3 * l];
        cols = (const int*)P.p[9 + 3 * l];
        vals = (const float*)P.p[10 + 3 * l];
    }
    int r = __ldcs(rows + el);
    int c = __ldcs(cols + el);
    float v = __ldcs(vals + el);
    int p = atomicAdd(&g_pos[l * NT_ + r], 1);
    g_edges[p] = make_int2(c, __float_as_int(v));
}

// Batched CSR SpMM + residual; fp8 in, fp32 accumulate, fp8 out.
// 8 lanes per row; each lane covers 8 dims (one 8B fp8 load per edge).
// Edges loaded uniformly per 8-lane group (L1 broadcast). Final hop skips
// rows nobody reads via g_mask.
__global__ void __launch_bounds__(256) k_spmm_csr(int hop) {
    int tid = blockIdx.x * 256 + threadIdx.x;
    int row = tid >> 3;                 // global row in [0, NT4_); grid exact
    if (hop == 2 && !g_mask[row]) return;
    int k = tid & 7;
    const unsigned char* xg = (hop == 0) ? g_X8 : ((hop == 1) ? g_B1 : g_B2);
    unsigned char* y = (hop == 0) ? g_B1 : ((hop == 1) ? g_B2 : g_B3);
    int l = row / NT_;
    const unsigned char* xb = xg + (size_t)l * NT_ * D_;
    int s0 = g_rowptr[row];
    int s1 = g_rowptr[row + 1];
    float s[8] = {0.f, 0.f, 0.f, 0.f, 0.f, 0.f, 0.f, 0.f};
#pragma unroll 4
    for (int e = s0; e < s1; e++) {
        int2 ed = __ldcs(&g_edges[e]);  // uniform in 8-lane group -> broadcast
        float vj = __int_as_float(ed.y);
        uint2 raw = *(const uint2*)(xb + (size_t)ed.x * D_ + k * 8);
        fp8x4_acc_(raw.x, vj, s);
        fp8x4_acc_(raw.y, vj, s + 4);
    }
    size_t ro = (size_t)row * D_ + k * 8;
    // residual: + h[row]
    {
        uint2 raw = *(const uint2*)(xg + ro);
        fp8x4_acc_(raw.x, 1.f, s);
        fp8x4_acc_(raw.y, 1.f, s + 4);
    }
    // store y (fp8)
    uint2 o;
    o.x = f4_to_fp8x4_(s[0], s[1], s[2], s[3]);
    o.y = f4_to_fp8x4_(s[4], s[5], s[6], s[7]);
    *(uint2*)(y + ro) = o;
}

// ---------------------------------------------------------------------------
// Loss kernels: reconstruct 0.25*(h0 + (h1+h2+h3)/64) on the fly.

__global__ void __launch_bounds__(256) k_rating(const int* __restrict__ user,
                                                const int* __restrict__ pos,
                                                const int* __restrict__ neg,
                                                const float* __restrict__ ue,
                                                const float* __restrict__ ie) {
    int gt = blockIdx.x * 256 + threadIdx.x;
    int w = gt >> 5, lane = gt & 31;
    if (w >= 8192) return;
    int ur = user[w];
    int pr = pos[w];
    int nr = neg[w];
    float pp = 0.f, np = 0.f, l2 = 0.f;
#pragma unroll
    for (int q = 0; q < 2; q++) {
        int d = lane * 2 + q;
        float u = acc4_(ue, ur, ur, d);                  // layer 0, user
        float a = acc4_(ie, pr, (size_t)NU_ + pr, d);    // layer 0, item
        float b = acc4_(ie, nr, (size_t)NU_ + nr, d);
        pp += u * a;
        np += u * b;
        l2 += u * u + a * a + b * b;
    }
    for (int o = 16; o; o >>= 1) {
        pp += __shfl_down_sync(0xffffffffu, pp, o);
        np += __shfl_down_sync(0xffffffffu, np, o);
        l2 += __shfl_down_sync(0xffffffffu, l2, o);
    }
    if (lane == 0) atomicAdd(&g_scal[0], sp_(np - pp) + 0.01f * l2);
}

// Sum of -softplus(sign*acc) over 4096 gathered user rows of layer at rowoff.
__global__ void __launch_bounds__(256) k_brilog(const int* __restrict__ idx,
                                                const float* __restrict__ emb,
                                                int rowoff, float sign, int slot) {
    int t = blockIdx.x * 256 + threadIdx.x;  // exactly 4096*64 threads
    int i = t >> 6, d = t & 63;
    int r = idx[i];
    float x = acc4_(emb, r, (size_t)rowoff + r, d);
    float val = -sp_(sign * x);
    __shared__ float sm[256];
    sm[threadIdx.x] = val;
    __syncthreads();
    for (int s = 128; s; s >>= 1) {
        if (threadIdx.x < s) sm[threadIdx.x] += sm[threadIdx.x + s];
        __syncthreads();
    }
    if (threadIdx.x == 0) atomicAdd(&g_scal[slot], sm[0]);
}

// Column sums of acc over layer-2 user rows [BRI_, BRI_+50000) -> g_scal[8+d].
__global__ void __launch_bounds__(256) k_gsoc(const float* __restrict__ sgu) {
    int gt = blockIdx.x * 256 + threadIdx.x;  // 128 blocks -> 512 row groups
    int d = gt & 63;
    int rg = gt >> 6;
    const size_t base = (size_t)2 * NT_;  // layer 2 global row offset
    float s = 0.f;
    for (int r = BRI_ + rg; r < BRI_ + 50000; r += 512)
        s += acc4_(sgu, r, base + r, d);
    __shared__ float sm[256];
    sm[threadIdx.x] = s;
    __syncthreads();
    if (threadIdx.x < 64)
        atomicAdd(&g_scal[8 + threadIdx.x],
                  sm[threadIdx.x] + sm[threadIdx.x + 64] +
                  sm[threadIdx.x + 128] + sm[threadIdx.x + 192]);
}

// Column sums of sigmoid(acc) over 4096 gathered rows -> g_scal[slot+d].
__global__ void __launch_bounds__(256) k_gmean(const int* __restrict__ idx,
                                               const float* __restrict__ emb,
                                               int growoff, int slot) {
    int t = blockIdx.x * 256 + threadIdx.x;  // exactly 4096*64 threads
    int i = t >> 6, d = t & 63;
    int r = idx[i];
    float x = acc4_(emb, r, (size_t)growoff + r, d);
    float sg = 1.f / (1.f + expf(-x));
    __shared__ float sm[256];
    sm[threadIdx.x] = sg;
    __syncthreads();
    if (threadIdx.x < 64)
        atomicAdd(&g_scal[slot + threadIdx.x],
                  sm[threadIdx.x] + sm[threadIdx.x + 64] +
                  sm[threadIdx.x + 128] + sm[threadIdx.x + 192]);
}

__global__ void k_final(float* __restrict__ out) {
    double sgr = 0.0, sgf = 0.0, sir = 0.0, sif = 0.0;
    for (int d = 0; d < 64; d++) {
        double gs = (double)g_scal[8 + d] / 50000.0;
        double sg = 1.0 / (1.0 + exp(-gs));
        sgr += log(sg);
        sgf += log(1.0 - sg);
    }
    for (int d = 0; d < 128; d++) {
        double g = (double)g_scal[72 + d] / 4096.0;
        sir += log(g);
        sif += log1p(-g);
    }
    double A1 = g_scal[0], A2 = g_scal[1], A3 = g_scal[2];
    double A5 = g_scal[3], A6 = g_scal[4];
    double social = -(A2 / (4096.0 * 128.0) + sgr / 128.0)
                    - (A3 / (4096.0 * 128.0) + sgf / 128.0);
    double infor  = -(A5 / (4096.0 * 192.0) + sir / 192.0)
                    - (A6 / (4096.0 * 192.0) + sif / 192.0);
    double rating = A1;
    double obj = rating + 100.0 * social + 1000.0 * infor;
    out[0] = (float)obj;
    out[1] = (float)rating;
    out[2] = (float)social;
    out[3] = (float)infor;
}

extern "C" void kernel_launch(void* const* d_in, const int* in_sizes, int n_in,
                              void* d_out, int out_size) {
    Ptrs P;
    for (int i = 0; i < 26; i++) P.p[i] = d_in[i];
    const float* ue  = (const float*)d_in[0];
    const float* ie  = (const float*)d_in[1];
    const float* fue = (const float*)d_in[2];
    const float* sgu = (const float*)d_in[4];
    const float* igu = (const float*)d_in[6];
    const float* igi = (const float*)d_in[7];
    const int* user      = (const int*)d_in[20];
    const int* pos       = (const int*)d_in[21];
    const int* neg       = (const int*)d_in[22];
    const int* s_bri     = (const int*)d_in[23];
    const int* i_bri     = (const int*)d_in[24];
    const int* i_bri_pos = (const int*)d_in[25];

    k_setup<<<1, 256>>>((const unsigned*)d_in[8]);

    const int CHG4 = (NT4_ * D_ / 8 + 255) / 256;  // 18750
    const int EDG4 = (NNZ4_ + 255) / 256;          // 37500
    const int SPG4 = (NT4_ * 8) / 256;             // 18750 exact

    k_init<<<CHG4, 256>>>(P);
    k_mark<<<(99152 + 255) / 256, 256>>>(user, pos, neg, s_bri, i_bri, i_bri_pos);
    k_hist<<<EDG4, 256>>>(P);
    k_scanA<<<SCB4_, 1024>>>();
    k_scanB<<<1, 1024>>>();
    k_scanC<<<SCB4_, 1024>>>();
    k_scatter<<<EDG4, 256>>>(P);
    for (int hop = 0; hop < 3; hop++)
        k_spmm_csr<<<SPG4, 256>>>(hop);

    k_rating<<<1024, 256>>>(user, pos, neg, ue, ie);
    k_brilog<<<1024, 256>>>(s_bri, ue, 0, -1.f, 1);               // layer 0
    k_brilog<<<1024, 256>>>(i_bri, ue, 0, -1.f, 3);               // layer 0
    k_brilog<<<1024, 256>>>(s_bri, fue, NT_, 1.f, 2);             // layer 1
    k_brilog<<<1024, 256>>>(i_bri, fue, NT_, 1.f, 4);             // layer 1
    k_gsoc<<<128, 256>>>(sgu);                                    // layer 2
    k_gmean<<<1024, 256>>>(i_bri, igu, 3 * NT_, 72);              // layer 3 users
    k_gmean<<<1024, 256>>>(i_bri_pos, igi, 3 * NT_ + NU_, 136);   // layer 3 items
    k_final<<<1, 1>>>((float*)d_out);
}

// round 16
// speedup vs baseline: 1.3642x; 1.0045x over previous
#include <cuda_runtime.h>
#include <cuda_bf16.h>
#include <cuda_fp8.h>
#include <math.h>

#define NU_  100000
#define NI_  50000
#define NT_  150000
#define NT4_ 600000          // 4 layers concatenated
#define D_   64
#define NNZ_ 2400000
#define NNZ4_ 9600000
#define BRI_ 50000
#define SCB4_ 586            // ceil(600000/1024)

#define SCALE_   64.0f
#define SCALE_I  (1.0f / 64.0f)

// Hop buffers in e4m3 fp8, uniformly scaled by 64 (propagation is linear, so
// the scale passes through hops exactly; losses divide it out).
// h0 is re-read from the fp32 inputs at loss time; h1..h3 live here.
__device__ unsigned char g_X8[(size_t)NT4_ * D_];
__device__ unsigned char g_B1[(size_t)NT4_ * D_];
__device__ unsigned char g_B2[(size_t)NT4_ * D_];
__device__ unsigned char g_B3[(size_t)NT4_ * D_];
// Unified CSR across 4 adjacencies
__device__ int  g_rowptr[NT4_ + 1];
__device__ int  g_cnt[NT4_];
__device__ int  g_pos[NT4_];
__device__ int2 g_edges[NNZ4_];  // (local col, float_bits(val))
__device__ int  g_bsum[SCB4_];
__device__ int  g_boff[SCB4_];
// Which rows' hop-3 outputs are actually consumed by the losses.
__device__ unsigned char g_mask[NT4_];
// Scalar accumulators + ordering flag
__device__ float g_scal[256];
__device__ int g_ordB;

struct Ptrs { const void* p[26]; };

__device__ __forceinline__ float sp_(float x) {  // softplus
    return (x > 15.f) ? x : log1pf(expf(x));
}

__device__ __forceinline__ float fp8_to_f_(unsigned char v) {
    __half_raw h = __nv_cvt_fp8_to_halfraw((__nv_fp8_storage_t)v, __NV_E4M3);
    return __half2float(*(__half*)&h);
}

// Accumulate 4 fp8 dims (one 32-bit word) into s[0..3] with weight vj.
__device__ __forceinline__ void fp8x4_acc_(unsigned raw, float vj, float* s) {
    __half2_raw h0 = __nv_cvt_fp8x2_to_halfraw2(
        (__nv_fp8x2_storage_t)(raw & 0xFFFFu), __NV_E4M3);
    __half2_raw h1 = __nv_cvt_fp8x2_to_halfraw2(
        (__nv_fp8x2_storage_t)(raw >> 16), __NV_E4M3);
    float2 f0 = __half22float2(*(__half2*)&h0);
    float2 f1 = __half22float2(*(__half2*)&h1);
    s[0] += vj * f0.x;
    s[1] += vj * f0.y;
    s[2] += vj * f1.x;
    s[3] += vj * f1.y;
}

// Pack 4 floats into 4 fp8 bytes (one 32-bit word).
__device__ __forceinline__ unsigned f4_to_fp8x4_(float a, float b, float c, float d) {
    unsigned lo = __nv_cvt_float2_to_fp8x2(make_float2(a, b), __NV_SATFINITE, __NV_E4M3);
    unsigned hi = __nv_cvt_float2_to_fp8x2(make_float2(c, d), __NV_SATFINITE, __NV_E4M3);
    return (hi << 16) | (lo & 0xFFFFu);
}

// acc(row) = 0.25*(h0 + (h1+h2+h3)/64); h0 from the fp32 input embedding.
__device__ __forceinline__ float acc4_(const float* __restrict__ emb,
                                       size_t elocal, size_t grow, int d) {
    float h0 = emb[elocal * D_ + d];
    size_t o = grow * D_ + d;
    float h123 = fp8_to_f_(g_B1[o]) + fp8_to_f_(g_B2[o]) + fp8_to_f_(g_B3[o]);
    return 0.25f * (h0 + h123 * SCALE_I);
}

// ---------------------------------------------------------------------------
// Zero scalar accumulators + detect input ordering by inspecting d_in[8]:
// int32 node ids < 150000 have bit patterns < 0x04000000; uniform floats don't.
__global__ void k_setup(const unsigned* __restrict__ p8) {
    int t = threadIdx.x;
    if (t < 256) g_scal[t] = 0.f;
    if (t == 0) {
        int fl = 0;
        for (int i = 0; i < 64; i++)
            if (p8[i] > 0x04000000u) fl++;
        g_ordB = (fl > 32) ? 1 : 0;
    }
}

// Batched: X8(fp8, x64) = concat(user_emb, item_emb); zero histogram + mask.
__global__ void __launch_bounds__(256) k_init(Ptrs P) {
    const int PL = NT_ * D_ / 8;  // 1.2M chunks per layer
    int i = blockIdx.x * 256 + threadIdx.x;
    if (i >= 4 * PL) return;
    if (i < NT4_) { g_cnt[i] = 0; g_mask[i] = 0; }
    int l = i / PL;
    int f = (i - l * PL) * 8;
    const float* eu = (const float*)P.p[2 * l];
    const float* ei = (const float*)P.p[2 * l + 1];
    const float* src = (f < NU_ * D_) ? (eu + f) : (ei + (f - NU_ * D_));
    float4 a = *(const float4*)(src);
    float4 b = *(const float4*)(src + 4);
    uint2 o;
    o.x = f4_to_fp8x4_(a.x * SCALE_, a.y * SCALE_, a.z * SCALE_, a.w * SCALE_);
    o.y = f4_to_fp8x4_(b.x * SCALE_, b.y * SCALE_, b.z * SCALE_, b.w * SCALE_);
    *(uint2*)(g_X8 + (size_t)l * NT_ * D_ + f) = o;
}

// Mark the rows whose final-hop output is consumed by a loss.
__global__ void __launch_bounds__(256) k_mark(const int* __restrict__ user,
                                             const int* __restrict__ pos,
                                             const int* __restrict__ neg,
                                             const int* __restrict__ s_bri,
                                             const int* __restrict__ i_bri,
                                             const int* __restrict__ i_bri_pos) {
    int t = blockIdx.x * 256 + threadIdx.x;
    int r = -1;
    if      (t < 8192)           r = user[t];                       // L0 user
    else if (t < 16384)          r = NU_ + pos[t - 8192];           // L0 item
    else if (t < 24576)          r = NU_ + neg[t - 16384];          // L0 item
    else if (t < 28672)          r = s_bri[t - 24576];              // L0
    else if (t < 32768)          r = i_bri[t - 28672];              // L0
    else if (t < 36864)          r = NT_ + s_bri[t - 32768];        // L1
    else if (t < 40960)          r = NT_ + i_bri[t - 36864];        // L1
    else if (t < 45056)          r = 3 * NT_ + i_bri[t - 40960];    // L3 user
    else if (t < 49152)          r = 3 * NT_ + NU_ + i_bri_pos[t - 45056]; // L3 item
    else if (t < 99152)          r = 2 * NT_ + BRI_ + (t - 49152);  // L2 range
    if (r >= 0) g_mask[r] = 1;
}

// Batched histogram over all 4 adjacencies.
__global__ void __launch_bounds__(256) k_hist(Ptrs P) {
    int e = blockIdx.x * 256 + threadIdx.x;
    if (e >= NNZ4_) return;
    int l = e / NNZ_;
    int el = e - l * NNZ_;
    const int* rows = g_ordB ? (const int*)P.p[12 + 2 * l]
                             : (const int*)P.p[8 + 3 * l];
    atomicAdd(&g_cnt[l * NT_ + __ldcs(rows + el)], 1);
}

// Multi-block scan over 600K counts, phase A: per-block sums.
__global__ void __launch_bounds__(1024) k_scanA() {
    __shared__ int sm[1024];
    int t = threadIdx.x;
    int i = blockIdx.x * 1024 + t;
    sm[t] = (i < NT4_) ? g_cnt[i] : 0;
    __syncthreads();
    for (int s = 512; s; s >>= 1) {
        if (t < s) sm[t] += sm[t + s];
        __syncthreads();
    }
    if (t == 0) g_bsum[blockIdx.x] = sm[0];
}

// Phase B: single block scans the 586 block sums (exclusive).
__global__ void __launch_bounds__(1024) k_scanB() {
    __shared__ int sm[1024];
    int t = threadIdx.x;
    int v = (t < SCB4_) ? g_bsum[t] : 0;
    sm[t] = v;
    __syncthreads();
    for (int o = 1; o < 1024; o <<= 1) {
        int u = (t >= o) ? sm[t - o] : 0;
        __syncthreads();
        sm[t] += u;
        __syncthreads();
    }
    if (t < SCB4_) g_boff[t] = sm[t] - v;
}

// Phase C: per-block local scan + global offset -> rowptr, pos.
__global__ void __launch_bounds__(1024) k_scanC() {
    __shared__ int sm[1024];
    int t = threadIdx.x;
    int i = blockIdx.x * 1024 + t;
    int v = (i < NT4_) ? g_cnt[i] : 0;
    sm[t] = v;
    __syncthreads();
    for (int o = 1; o < 1024; o <<= 1) {
        int u = (t >= o) ? sm[t - o] : 0;
        __syncthreads();
        sm[t] += u;
        __syncthreads();
    }
    int excl = g_boff[blockIdx.x] + sm[t] - v;
    if (i < NT4_) {
        g_rowptr[i] = excl;
        g_pos[i] = excl;
    }
    if (i == NT4_ - 1) g_rowptr[NT4_] = excl + v;
}

// Batched scatter (fp-sum order nondeterminism ~1e-7, tol 1e-3).
__global__ void __launch_bounds__(256) k_scatter(Ptrs P) {
    int e = blockIdx.x * 256 + threadIdx.x;
    if (e >= NNZ4_) return;
    int l = e / NNZ_;
    int el = e - l * NNZ_;
    const int *rows, *cols;
    const float* vals;
    if (g_ordB) {
        rows = (const int*)P.p[12 + 2 * l];
        cols = (const int*)P.p[13 + 2 * l];
        vals = (const float*)P.p[8 + l];
    } else {
        rows = (const int*)P.p[8 + 3 * l];
        cols = (const int*)P.p[9 + 3 * l];
        vals = (const float*)P.p[10 + 3 * l];
    }
    int r = __ldcs(rows + el);
    int c = __ldcs(cols + el);
    float v = __ldcs(vals + el);
    int p = atomicAdd(&g_pos[l * NT_ + r], 1);
    g_edges[p] = make_int2(c, __float_as_int(v));
}

// Batched CSR SpMM + residual; fp8 in, fp32 accumulate, fp8 out.
// 4 lanes per row; each lane covers 16 dims (one LDG.128 per edge per group),
// 8 rows per warp. Edges loaded uniformly per 4-lane group (L1 broadcast).
// Final hop skips rows nobody reads via g_mask.
__global__ void __launch_bounds__(256) k_spmm_csr(int hop) {
    int tid = blockIdx.x * 256 + threadIdx.x;
    int row = tid >> 2;                 // global row in [0, NT4_); grid exact
    if (hop == 2 && !g_mask[row]) return;
    int k = tid & 3;
    const unsigned char* xg = (hop == 0) ? g_X8 : ((hop == 1) ? g_B1 : g_B2);
    unsigned char* y = (hop == 0) ? g_B1 : ((hop == 1) ? g_B2 : g_B3);
    int l = row / NT_;
    const unsigned char* xb = xg + (size_t)l * NT_ * D_;
    int s0 = g_rowptr[row];
    int s1 = g_rowptr[row + 1];
    float s[16];
#pragma unroll
    for (int q = 0; q < 16; q++) s[q] = 0.f;
#pragma unroll 4
    for (int e = s0; e < s1; e++) {
        int2 ed = __ldcs(&g_edges[e]);  // uniform in 4-lane group -> broadcast
        float vj = __int_as_float(ed.y);
        uint4 raw = *(const uint4*)(xb + (size_t)ed.x * D_ + k * 16);
        fp8x4_acc_(raw.x, vj, s);
        fp8x4_acc_(raw.y, vj, s + 4);
        fp8x4_acc_(raw.z, vj, s + 8);
        fp8x4_acc_(raw.w, vj, s + 12);
    }
    size_t ro = (size_t)row * D_ + k * 16;
    // residual: + h[row]
    {
        uint4 raw = *(const uint4*)(xg + ro);
        fp8x4_acc_(raw.x, 1.f, s);
        fp8x4_acc_(raw.y, 1.f, s + 4);
        fp8x4_acc_(raw.z, 1.f, s + 8);
        fp8x4_acc_(raw.w, 1.f, s + 12);
    }
    // store y (fp8)
    uint4 o;
    o.x = f4_to_fp8x4_(s[0],  s[1],  s[2],  s[3]);
    o.y = f4_to_fp8x4_(s[4],  s[5],  s[6],  s[7]);
    o.z = f4_to_fp8x4_(s[8],  s[9],  s[10], s[11]);
    o.w = f4_to_fp8x4_(s[12], s[13], s[14], s[15]);
    *(uint4*)(y + ro) = o;
}

// ---------------------------------------------------------------------------
// Loss kernels: reconstruct 0.25*(h0 + (h1+h2+h3)/64) on the fly.

__global__ void __launch_bounds__(256) k_rating(const int* __restrict__ user,
                                                const int* __restrict__ pos,
                                                const int* __restrict__ neg,
                                                const float* __restrict__ ue,
                                                const float* __restrict__ ie) {
    int gt = blockIdx.x * 256 + threadIdx.x;
    int w = gt >> 5, lane = gt & 31;
    if (w >= 8192) return;
    int ur = user[w];
    int pr = pos[w];
    int nr = neg[w];
    float pp = 0.f, np = 0.f, l2 = 0.f;
#pragma unroll
    for (int q = 0; q < 2; q++) {
        int d = lane * 2 + q;
        float u = acc4_(ue, ur, ur, d);                  // layer 0, user
        float a = acc4_(ie, pr, (size_t)NU_ + pr, d);    // layer 0, item
        float b = acc4_(ie, nr, (size_t)NU_ + nr, d);
        pp += u * a;
        np += u * b;
        l2 += u * u + a * a + b * b;
    }
    for (int o = 16; o; o >>= 1) {
        pp += __shfl_down_sync(0xffffffffu, pp, o);
        np += __shfl_down_sync(0xffffffffu, np, o);
        l2 += __shfl_down_sync(0xffffffffu, l2, o);
    }
    if (lane == 0) atomicAdd(&g_scal[0], sp_(np - pp) + 0.01f * l2);
}

// Sum of -softplus(sign*acc) over 4096 gathered user rows of layer at rowoff.
__global__ void __launch_bounds__(256) k_brilog(const int* __restrict__ idx,
                                                const float* __restrict__ emb,
                                                int rowoff, float sign, int slot) {
    int t = blockIdx.x * 256 + threadIdx.x;  // exactly 4096*64 threads
    int i = t >> 6, d = t & 63;
    int r = idx[i];
    float x = acc4_(emb, r, (size_t)rowoff + r, d);
    float val = -sp_(sign * x);
    __shared__ float sm[256];
    sm[threadIdx.x] = val;
    __syncthreads();
    for (int s = 128; s; s >>= 1) {
        if (threadIdx.x < s) sm[threadIdx.x] += sm[threadIdx.x + s];
        __syncthreads();
    }
    if (threadIdx.x == 0) atomicAdd(&g_scal[slot], sm[0]);
}

// Column sums of acc over layer-2 user rows [BRI_, BRI_+50000) -> g_scal[8+d].
__global__ void __launch_bounds__(256) k_gsoc(const float* __restrict__ sgu) {
    int gt = blockIdx.x * 256 + threadIdx.x;  // 128 blocks -> 512 row groups
    int d = gt & 63;
    int rg = gt >> 6;
    const size_t base = (size_t)2 * NT_;  // layer 2 global row offset
    float s = 0.f;
    for (int r = BRI_ + rg; r < BRI_ + 50000; r += 512)
        s += acc4_(sgu, r, base + r, d);
    __shared__ float sm[256];
    sm[threadIdx.x] = s;
    __syncthreads();
    if (threadIdx.x < 64)
        atomicAdd(&g_scal[8 + threadIdx.x],
                  sm[threadIdx.x] + sm[threadIdx.x + 64] +
                  sm[threadIdx.x + 128] + sm[threadIdx.x + 192]);
}

// Column sums of sigmoid(acc) over 4096 gathered rows -> g_scal[slot+d].
__global__ void __launch_bounds__(256) k_gmean(const int* __restrict__ idx,
                                               const float* __restrict__ emb,
                                               int growoff, int slot) {
    int t = blockIdx.x * 256 + threadIdx.x;  // exactly 4096*64 threads
    int i = t >> 6, d = t & 63;
    int r = idx[i];
    float x = acc4_(emb, r, (size_t)growoff + r, d);
    float sg = 1.f / (1.f + expf(-x));
    __shared__ float sm[256];
    sm[threadIdx.x] = sg;
    __syncthreads();
    if (threadIdx.x < 64)
        atomicAdd(&g_scal[slot + threadIdx.x],
                  sm[threadIdx.x] + sm[threadIdx.x + 64] +
                  sm[threadIdx.x + 128] + sm[threadIdx.x + 192]);
}

__global__ void k_final(float* __restrict__ out) {
    double sgr = 0.0, sgf = 0.0, sir = 0.0, sif = 0.0;
    for (int d = 0; d < 64; d++) {
        double gs = (double)g_scal[8 + d] / 50000.0;
        double sg = 1.0 / (1.0 + exp(-gs));
        sgr += log(sg);
        sgf += log(1.0 - sg);
    }
    for (int d = 0; d < 128; d++) {
        double g = (double)g_scal[72 + d] / 4096.0;
        sir += log(g);
        sif += log1p(-g);
    }
    double A1 = g_scal[0], A2 = g_scal[1], A3 = g_scal[2];
    double A5 = g_scal[3], A6 = g_scal[4];
    double social = -(A2 / (4096.0 * 128.0) + sgr / 128.0)
                    - (A3 / (4096.0 * 128.0) + sgf / 128.0);
    double infor  = -(A5 / (4096.0 * 192.0) + sir / 192.0)
                    - (A6 / (4096.0 * 192.0) + sif / 192.0);
    double rating = A1;
    double obj = rating + 100.0 * social + 1000.0 * infor;
    out[0] = (float)obj;
    out[1] = (float)rating;
    out[2] = (float)social;
    out[3] = (float)infor;
}

extern "C" void kernel_launch(void* const* d_in, const int* in_sizes, int n_in,
                              void* d_out, int out_size) {
    Ptrs P;
    for (int i = 0; i < 26; i++) P.p[i] = d_in[i];
    const float* ue  = (const float*)d_in[0];
    const float* ie  = (const float*)d_in[1];
    const float* fue = (const float*)d_in[2];
    const float* sgu = (const float*)d_in[4];
    const float* igu = (const float*)d_in[6];
    const float* igi = (const float*)d_in[7];
    const int* user      = (const int*)d_in[20];
    const int* pos       = (const int*)d_in[21];
    const int* neg       = (const int*)d_in[22];
    const int* s_bri     = (const int*)d_in[23];
    const int* i_bri     = (const int*)d_in[24];
    const int* i_bri_pos = (const int*)d_in[25];

    k_setup<<<1, 256>>>((const unsigned*)d_in[8]);

    const int CHG4 = (NT4_ * D_ / 8 + 255) / 256;  // 18750
    const int EDG4 = (NNZ4_ + 255) / 256;          // 37500
    const int SPG4 = (NT4_ * 4) / 256;             // 9375 exact

    k_init<<<CHG4, 256>>>(P);
    k_mark<<<(99152 + 255) / 256, 256>>>(user, pos, neg, s_bri, i_bri, i_bri_pos);
    k_hist<<<EDG4, 256>>>(P);
    k_scanA<<<SCB4_, 1024>>>();
    k_scanB<<<1, 1024>>>();
    k_scanC<<<SCB4_, 1024>>>();
    k_scatter<<<EDG4, 256>>>(P);
    for (int hop = 0; hop < 3; hop++)
        k_spmm_csr<<<SPG4, 256>>>(hop);

    k_rating<<<1024, 256>>>(user, pos, neg, ue, ie);
    k_brilog<<<1024, 256>>>(s_bri, ue, 0, -1.f, 1);               // layer 0
    k_brilog<<<1024, 256>>>(i_bri, ue, 0, -1.f, 3);               // layer 0
    k_brilog<<<1024, 256>>>(s_bri, fue, NT_, 1.f, 2);             // layer 1
    k_brilog<<<1024, 256>>>(i_bri, fue, NT_, 1.f, 4);             // layer 1
    k_gsoc<<<128, 256>>>(sgu);                                    // layer 2
    k_gmean<<<1024, 256>>>(i_bri, igu, 3 * NT_, 72);              // layer 3 users
    k_gmean<<<1024, 256>>>(i_bri_pos, igi, 3 * NT_ + NU_, 136);   // layer 3 items
    k_final<<<1, 1>>>((float*)d_out);
}